// round 11
// baseline (speedup 1.0000x reference)
#include <cuda_runtime.h>
#include <cuda_fp16.h>
#include <cstdint>

// Problem constants (fixed by the dataset)
#define NN   4096
#define FDIM 256
#define BB   8
#define MTOT (BB * NN)          // 32768 rows
#define WPR  (NN / 32)
#define MAXD 128

// -------- scratch (static __device__ arrays; no allocation allowed) --------
__device__ unsigned g_adj[NN * WPR];
__device__ int      g_deg[NN];
__device__ int      g_nbr[NN * MAXD];
__device__ __align__(16) __half g_xth[(size_t)MTOT * FDIM];  // 16 MB fp16 xt
__device__ __align__(16) __half g_wt[FDIM * FDIM];           // W^T fp16 [n][k]

// ---------------------------------------------------------------------------
// Kernel 1: fused init — zero bitmask+degree AND weight transpose (fp16)
// ---------------------------------------------------------------------------
__global__ void k_init(const float* __restrict__ w) {
    int i = blockIdx.x * blockDim.x + threadIdx.x;
    ((uint4*)g_adj)[i] = make_uint4(0u, 0u, 0u, 0u);   // 131072 uint4 = whole g_adj
    if (i < NN) g_deg[i] = 0;
    if (i < FDIM * FDIM) {
        int k = i >> 8, n = i & 255;
        g_wt[n * FDIM + k] = __float2half_rn(w[i]);
    }
}

// ---------------------------------------------------------------------------
// Kernel 2: build dedup'd neighbor lists
// ---------------------------------------------------------------------------
__global__ void k_edges(const int* __restrict__ ei, int E) {
    int e = blockIdx.x * blockDim.x + threadIdx.x;
    if (e >= E) return;
    int src = ei[e];
    int dst = ei[E + e];
    unsigned mask = 1u << (dst & 31);
    unsigned old = atomicOr(&g_adj[src * WPR + (dst >> 5)], mask);
    if (!(old & mask)) {
        int pos = atomicAdd(&g_deg[src], 1);
        if (pos < MAXD) g_nbr[src * MAXD + pos] = dst;
    }
}

// ---------------------------------------------------------------------------
// Kernel 3: xt = x @ W via single-term fp16 mma.sync (fp32 accumulate).
// CTA tile M=128 x N=128; A fragments from global reused across both
// n-halves. B (128 n x 256 k fp16) resident in smem. (unchanged, round 10)
// ---------------------------------------------------------------------------
#define BSTR  264                 // B smem row stride in halves (256 + 8 pad)
#define S_TOT (128 * BSTR * 2)    // 67584 bytes

extern __shared__ char dsm[];

__device__ __forceinline__ uint32_t smem_u32(const void* p) {
    uint32_t a;
    asm("{ .reg .u64 t; cvta.to.shared.u64 t, %1; cvt.u32.u64 %0, t; }"
        : "=r"(a) : "l"(p));
    return a;
}
__device__ __forceinline__ void ldsm_x4(uint32_t* r, uint32_t addr) {
    asm volatile("ldmatrix.sync.aligned.m8n8.x4.shared.b16 {%0,%1,%2,%3}, [%4];"
                 : "=r"(r[0]), "=r"(r[1]), "=r"(r[2]), "=r"(r[3]) : "r"(addr));
}
__device__ __forceinline__ void mma_f16(float* c, const uint32_t* a,
                                        const uint32_t* b) {
    asm volatile(
        "mma.sync.aligned.m16n8k16.row.col.f32.f16.f16.f32 "
        "{%0,%1,%2,%3}, {%4,%5,%6,%7}, {%8,%9}, {%0,%1,%2,%3};"
        : "+f"(c[0]), "+f"(c[1]), "+f"(c[2]), "+f"(c[3])
        : "r"(a[0]), "r"(a[1]), "r"(a[2]), "r"(a[3]), "r"(b[0]), "r"(b[1]));
}

__global__ void __launch_bounds__(256)
k_gemm_tc(const float* __restrict__ x) {
    const int tid  = threadIdx.x;
    const int lane = tid & 31;
    const int w    = tid >> 5;
    const int wm   = w >> 1;          // 0..3 (32-row block)
    const int wn   = w & 1;           // 0..1 (64-col block)
    const int n0   = blockIdx.x * 128;
    const int m0   = blockIdx.y * 128;
    const uint32_t sb = smem_u32(dsm);

    #pragma unroll
    for (int q = 0; q < 16; q++) {
        int idx = q * 256 + tid;
        int n = idx >> 5;
        int u = idx & 31;
        *(uint4*)(dsm + n * (BSTR * 2) + u * 16) =
            *(const uint4*)&g_wt[(size_t)(n0 + n) * FDIM + u * 8];
    }
    __syncthreads();

    const float* ap = x + (size_t)(m0 + wm * 32 + (lane >> 2)) * FDIM +
                      ((lane & 3) << 1);
    const uint32_t bbase = sb +
        (uint32_t)(wn * 64 + ((lane >> 4) & 1) * 8 + (lane & 7)) * (BSTR * 2) +
        (uint32_t)(((lane >> 3) & 1) * 8) * 2;

    float acc[2][8][4];
    #pragma unroll
    for (int i = 0; i < 2; i++)
        #pragma unroll
        for (int j = 0; j < 8; j++)
            #pragma unroll
            for (int r = 0; r < 4; r++) acc[i][j][r] = 0.f;

    float2 pv[2][4];
    #pragma unroll
    for (int i = 0; i < 2; i++) {
        const float* p = ap + i * 16 * FDIM;
        pv[i][0] = *(const float2*)(p);
        pv[i][1] = *(const float2*)(p + 8 * FDIM);
        pv[i][2] = *(const float2*)(p + 8);
        pv[i][3] = *(const float2*)(p + 8 * FDIM + 8);
    }

    #pragma unroll
    for (int kk = 0; kk < 16; kk++) {
        float2 nv[2][4];
        if (kk + 1 < 16) {
            const int kn = (kk + 1) * 16;
            #pragma unroll
            for (int i = 0; i < 2; i++) {
                const float* p = ap + i * 16 * FDIM + kn;
                nv[i][0] = *(const float2*)(p);
                nv[i][1] = *(const float2*)(p + 8 * FDIM);
                nv[i][2] = *(const float2*)(p + 8);
                nv[i][3] = *(const float2*)(p + 8 * FDIM + 8);
            }
        }

        uint32_t aF[2][4];
        #pragma unroll
        for (int i = 0; i < 2; i++)
            #pragma unroll
            for (int q = 0; q < 4; q++) {
                __half2 h = __float22half2_rn(pv[i][q]);
                aF[i][q] = *(uint32_t*)&h;
            }

        const uint32_t kb = (uint32_t)(kk * 16) * 2;
        #pragma unroll
        for (int j2 = 0; j2 < 4; j2++) {
            uint32_t bb[4];
            ldsm_x4(bb, bbase + kb + (uint32_t)(j2 * 16) * (BSTR * 2));
            #pragma unroll
            for (int i = 0; i < 2; i++) {
                mma_f16(acc[i][2 * j2 + 0], aF[i], &bb[0]);
                mma_f16(acc[i][2 * j2 + 1], aF[i], &bb[2]);
            }
        }

        #pragma unroll
        for (int i = 0; i < 2; i++)
            #pragma unroll
            for (int q = 0; q < 4; q++) pv[i][q] = nv[i][q];
    }

    #pragma unroll
    for (int i = 0; i < 2; i++) {
        #pragma unroll
        for (int j = 0; j < 8; j++) {
            int m = m0 + wm * 32 + i * 16 + (lane >> 2);
            int n = n0 + wn * 64 + j * 8 + (lane & 3) * 2;
            *(__half2*)&g_xth[(size_t)m * FDIM + n] =
                __float22half2_rn(make_float2(acc[i][j][0], acc[i][j][1]));
            *(__half2*)&g_xth[(size_t)(m + 8) * FDIM + n] =
                __float22half2_rn(make_float2(acc[i][j][2], acc[i][j][3]));
        }
    }
}

// ---------------------------------------------------------------------------
// Kernel 4: sparse aggregation. Warp = batch; lane owns 8 features via one
// LDG.128 per neighbor. 8-way neighbor unroll (MLP 8); pairwise HADD2
// pre-sums (same error model as round 9/10); fp32 accumulation.
// ---------------------------------------------------------------------------
__global__ void __launch_bounds__(256)
k_agg(const float* __restrict__ bias, float* __restrict__ out) {
    const int src  = blockIdx.x;
    const int tid  = threadIdx.x;
    const int b    = tid >> 5;           // batch = warp
    const int lane = tid & 31;
    const int f    = lane << 3;          // 8 features per lane

    __shared__ int snb[MAXD];
    int deg = g_deg[src];
    if (deg > MAXD) deg = MAXD;
    if (tid < deg) snb[tid] = g_nbr[src * MAXD + tid];
    __syncthreads();

    const __half* __restrict__ base = g_xth + (size_t)b * NN * FDIM + f;

    float acc[8];
    #pragma unroll
    for (int q = 0; q < 8; q++) acc[q] = 0.f;

    int i = 0;
    // 8-way unroll: 8 outstanding LDG.128 per lane
    for (; i + 8 <= deg; i += 8) {
        uint4 u[8];
        #pragma unroll
        for (int r = 0; r < 8; r++)
            u[r] = *(const uint4*)(base + ((size_t)snb[i + r] << 8));
        #pragma unroll
        for (int q = 0; q < 4; q++) {
            __half2 s01 = __hadd2(((const __half2*)&u[0])[q],
                                  ((const __half2*)&u[1])[q]);
            __half2 s23 = __hadd2(((const __half2*)&u[2])[q],
                                  ((const __half2*)&u[3])[q]);
            __half2 s45 = __hadd2(((const __half2*)&u[4])[q],
                                  ((const __half2*)&u[5])[q]);
            __half2 s67 = __hadd2(((const __half2*)&u[6])[q],
                                  ((const __half2*)&u[7])[q]);
            float2 f01 = __half22float2(s01);
            float2 f23 = __half22float2(s23);
            float2 f45 = __half22float2(s45);
            float2 f67 = __half22float2(s67);
            acc[2 * q]     += (f01.x + f23.x) + (f45.x + f67.x);
            acc[2 * q + 1] += (f01.y + f23.y) + (f45.y + f67.y);
        }
    }
    for (; i + 2 <= deg; i += 2) {
        uint4 u0 = *(const uint4*)(base + ((size_t)snb[i]     << 8));
        uint4 u1 = *(const uint4*)(base + ((size_t)snb[i + 1] << 8));
        #pragma unroll
        for (int q = 0; q < 4; q++) {
            __half2 s = __hadd2(((const __half2*)&u0)[q],
                                ((const __half2*)&u1)[q]);
            float2 fv = __half22float2(s);
            acc[2 * q]     += fv.x;
            acc[2 * q + 1] += fv.y;
        }
    }
    if (i < deg) {
        uint4 u0 = *(const uint4*)(base + ((size_t)snb[i] << 8));
        #pragma unroll
        for (int q = 0; q < 4; q++) {
            float2 fv = __half22float2(((const __half2*)&u0)[q]);
            acc[2 * q]     += fv.x;
            acc[2 * q + 1] += fv.y;
        }
    }

    const float inv = 1.0f / ((float)deg + 1e-6f);
    const float4 bf0 = *(const float4*)&bias[f];
    const float4 bf1 = *(const float4*)&bias[f + 4];

    float* dst = &out[((size_t)b * NN + src) * FDIM + f];
    *(float4*)(dst)     = make_float4(acc[0] * inv + bf0.x, acc[1] * inv + bf0.y,
                                      acc[2] * inv + bf0.z, acc[3] * inv + bf0.w);
    *(float4*)(dst + 4) = make_float4(acc[4] * inv + bf1.x, acc[5] * inv + bf1.y,
                                      acc[6] * inv + bf1.z, acc[7] * inv + bf1.w);
}

// ---------------------------------------------------------------------------
extern "C" void kernel_launch(void* const* d_in, const int* in_sizes, int n_in,
                              void* d_out, int out_size) {
    const float* x    = (const float*)d_in[0];   // (8, 4096, 256) f32
    const int*   ei   = (const int*)  d_in[1];   // (2, 131072) i32
    const float* w    = (const float*)d_in[2];   // (256, 256) f32
    const float* bias = (const float*)d_in[3];   // (256,) f32
    float* out = (float*)d_out;

    const int E = in_sizes[1] / 2;

    cudaFuncSetAttribute(k_gemm_tc, cudaFuncAttributeMaxDynamicSharedMemorySize,
                         S_TOT);

    k_init<<<512, 256>>>(w);
    k_edges<<<(E + 255) / 256, 256>>>(ei, E);
    k_gemm_tc<<<dim3(2, MTOT / 128), 256, S_TOT>>>(x);
    k_agg<<<NN, 256>>>(bias, out);
}

// round 12
// speedup vs baseline: 1.0284x; 1.0284x over previous
#include <cuda_runtime.h>
#include <cuda_fp16.h>
#include <cstdint>

// Problem constants (fixed by the dataset)
#define NN   4096
#define FDIM 256
#define BB   8
#define MTOT (BB * NN)          // 32768 rows
#define WPR  (NN / 32)
#define MAXD 128

// -------- scratch (static __device__ arrays; no allocation allowed) --------
// NOTE: g_adj and g_deg rely on CUDA's zero-initialization of __device__
// globals for the FIRST call; every call re-zeroes them in k_agg's tail,
// so they are zero at entry of every kernel_launch invocation.
__device__ unsigned g_adj[NN * WPR];
__device__ int      g_deg[NN];
__device__ int      g_nbr[NN * MAXD];
__device__ __align__(16) __half g_xth[(size_t)MTOT * FDIM];  // 16 MB fp16 xt
__device__ __align__(16) __half g_wt[FDIM * FDIM];           // W^T fp16 [n][k]

// ---------------------------------------------------------------------------
// Kernel 1: build dedup'd neighbor lists + fused weight transpose (fp16).
// Threads < 64K also write one g_wt element (coalesced write, scattered read).
// ---------------------------------------------------------------------------
__global__ void k_edges(const int* __restrict__ ei, const float* __restrict__ w,
                        int E) {
    int e = blockIdx.x * blockDim.x + threadIdx.x;
    if (e < FDIM * FDIM) {
        // g_wt[i] = W^T flat: i = n*256 + k  ->  w[k*256 + n]
        g_wt[e] = __float2half_rn(w[((e & 255) << 8) + (e >> 8)]);
    }
    if (e >= E) return;
    int src = ei[e];
    int dst = ei[E + e];
    unsigned mask = 1u << (dst & 31);
    unsigned old = atomicOr(&g_adj[src * WPR + (dst >> 5)], mask);
    if (!(old & mask)) {
        int pos = atomicAdd(&g_deg[src], 1);
        if (pos < MAXD) g_nbr[src * MAXD + pos] = dst;
    }
}

// ---------------------------------------------------------------------------
// Kernel 2: xt = x @ W via single-term fp16 mma.sync (fp32 accumulate).
// CTA tile M=128 x N=128; A fragments from global reused across both
// n-halves. B (128 n x 256 k fp16) resident in smem. (unchanged, round 10)
// ---------------------------------------------------------------------------
#define BSTR  264                 // B smem row stride in halves (256 + 8 pad)
#define S_TOT (128 * BSTR * 2)    // 67584 bytes

extern __shared__ char dsm[];

__device__ __forceinline__ uint32_t smem_u32(const void* p) {
    uint32_t a;
    asm("{ .reg .u64 t; cvta.to.shared.u64 t, %1; cvt.u32.u64 %0, t; }"
        : "=r"(a) : "l"(p));
    return a;
}
__device__ __forceinline__ void ldsm_x4(uint32_t* r, uint32_t addr) {
    asm volatile("ldmatrix.sync.aligned.m8n8.x4.shared.b16 {%0,%1,%2,%3}, [%4];"
                 : "=r"(r[0]), "=r"(r[1]), "=r"(r[2]), "=r"(r[3]) : "r"(addr));
}
__device__ __forceinline__ void mma_f16(float* c, const uint32_t* a,
                                        const uint32_t* b) {
    asm volatile(
        "mma.sync.aligned.m16n8k16.row.col.f32.f16.f16.f32 "
        "{%0,%1,%2,%3}, {%4,%5,%6,%7}, {%8,%9}, {%0,%1,%2,%3};"
        : "+f"(c[0]), "+f"(c[1]), "+f"(c[2]), "+f"(c[3])
        : "r"(a[0]), "r"(a[1]), "r"(a[2]), "r"(a[3]), "r"(b[0]), "r"(b[1]));
}

__global__ void __launch_bounds__(256)
k_gemm_tc(const float* __restrict__ x) {
    const int tid  = threadIdx.x;
    const int lane = tid & 31;
    const int w    = tid >> 5;
    const int wm   = w >> 1;          // 0..3 (32-row block)
    const int wn   = w & 1;           // 0..1 (64-col block)
    const int n0   = blockIdx.x * 128;
    const int m0   = blockIdx.y * 128;
    const uint32_t sb = smem_u32(dsm);

    #pragma unroll
    for (int q = 0; q < 16; q++) {
        int idx = q * 256 + tid;
        int n = idx >> 5;
        int u = idx & 31;
        *(uint4*)(dsm + n * (BSTR * 2) + u * 16) =
            *(const uint4*)&g_wt[(size_t)(n0 + n) * FDIM + u * 8];
    }
    __syncthreads();

    const float* ap = x + (size_t)(m0 + wm * 32 + (lane >> 2)) * FDIM +
                      ((lane & 3) << 1);
    const uint32_t bbase = sb +
        (uint32_t)(wn * 64 + ((lane >> 4) & 1) * 8 + (lane & 7)) * (BSTR * 2) +
        (uint32_t)(((lane >> 3) & 1) * 8) * 2;

    float acc[2][8][4];
    #pragma unroll
    for (int i = 0; i < 2; i++)
        #pragma unroll
        for (int j = 0; j < 8; j++)
            #pragma unroll
            for (int r = 0; r < 4; r++) acc[i][j][r] = 0.f;

    float2 pv[2][4];
    #pragma unroll
    for (int i = 0; i < 2; i++) {
        const float* p = ap + i * 16 * FDIM;
        pv[i][0] = *(const float2*)(p);
        pv[i][1] = *(const float2*)(p + 8 * FDIM);
        pv[i][2] = *(const float2*)(p + 8);
        pv[i][3] = *(const float2*)(p + 8 * FDIM + 8);
    }

    #pragma unroll
    for (int kk = 0; kk < 16; kk++) {
        float2 nv[2][4];
        if (kk + 1 < 16) {
            const int kn = (kk + 1) * 16;
            #pragma unroll
            for (int i = 0; i < 2; i++) {
                const float* p = ap + i * 16 * FDIM + kn;
                nv[i][0] = *(const float2*)(p);
                nv[i][1] = *(const float2*)(p + 8 * FDIM);
                nv[i][2] = *(const float2*)(p + 8);
                nv[i][3] = *(const float2*)(p + 8 * FDIM + 8);
            }
        }

        uint32_t aF[2][4];
        #pragma unroll
        for (int i = 0; i < 2; i++)
            #pragma unroll
            for (int q = 0; q < 4; q++) {
                __half2 h = __float22half2_rn(pv[i][q]);
                aF[i][q] = *(uint32_t*)&h;
            }

        const uint32_t kb = (uint32_t)(kk * 16) * 2;
        #pragma unroll
        for (int j2 = 0; j2 < 4; j2++) {
            uint32_t bb[4];
            ldsm_x4(bb, bbase + kb + (uint32_t)(j2 * 16) * (BSTR * 2));
            #pragma unroll
            for (int i = 0; i < 2; i++) {
                mma_f16(acc[i][2 * j2 + 0], aF[i], &bb[0]);
                mma_f16(acc[i][2 * j2 + 1], aF[i], &bb[2]);
            }
        }

        #pragma unroll
        for (int i = 0; i < 2; i++)
            #pragma unroll
            for (int q = 0; q < 4; q++) pv[i][q] = nv[i][q];
    }

    #pragma unroll
    for (int i = 0; i < 2; i++) {
        #pragma unroll
        for (int j = 0; j < 8; j++) {
            int m = m0 + wm * 32 + i * 16 + (lane >> 2);
            int n = n0 + wn * 64 + j * 8 + (lane & 3) * 2;
            *(__half2*)&g_xth[(size_t)m * FDIM + n] =
                __float22half2_rn(make_float2(acc[i][j][0], acc[i][j][1]));
            *(__half2*)&g_xth[(size_t)(m + 8) * FDIM + n] =
                __float22half2_rn(make_float2(acc[i][j][2], acc[i][j][3]));
        }
    }
}

// ---------------------------------------------------------------------------
// Kernel 3: sparse aggregation (round-10 proven 4-way loop) + rezero tail.
// Warp = batch; lane owns 8 features via one LDG.128 per neighbor.
// Tail: each block zeroes its own src's adjacency slab + degree so the
// next kernel_launch call starts from zeroed state.
// ---------------------------------------------------------------------------
__global__ void __launch_bounds__(256)
k_agg(const float* __restrict__ bias, float* __restrict__ out) {
    const int src  = blockIdx.x;
    const int tid  = threadIdx.x;
    const int b    = tid >> 5;           // batch = warp
    const int lane = tid & 31;
    const int f    = lane << 3;          // 8 features per lane

    __shared__ int snb[MAXD];
    int deg = g_deg[src];
    if (deg > MAXD) deg = MAXD;
    if (tid < deg) snb[tid] = g_nbr[src * MAXD + tid];
    __syncthreads();

    // ---- rezero for next call (all reads of g_deg/g_adj for this src done;
    //      each block touches only its own src's slots) ----
    if (tid < WPR) g_adj[src * WPR + tid] = 0u;
    if (tid == 0)  g_deg[src] = 0;

    const __half* __restrict__ base = g_xth + (size_t)b * NN * FDIM + f;

    float acc[8];
    #pragma unroll
    for (int q = 0; q < 8; q++) acc[q] = 0.f;

    int i = 0;
    for (; i + 4 <= deg; i += 4) {
        uint4 u0 = *(const uint4*)(base + ((size_t)snb[i]     << 8));
        uint4 u1 = *(const uint4*)(base + ((size_t)snb[i + 1] << 8));
        uint4 u2 = *(const uint4*)(base + ((size_t)snb[i + 2] << 8));
        uint4 u3 = *(const uint4*)(base + ((size_t)snb[i + 3] << 8));
        #pragma unroll
        for (int q = 0; q < 4; q++) {
            __half2 s01 = __hadd2(((const __half2*)&u0)[q],
                                  ((const __half2*)&u1)[q]);
            __half2 s23 = __hadd2(((const __half2*)&u2)[q],
                                  ((const __half2*)&u3)[q]);
            float2 f01 = __half22float2(s01);
            float2 f23 = __half22float2(s23);
            acc[2 * q]     += f01.x + f23.x;
            acc[2 * q + 1] += f01.y + f23.y;
        }
    }
    for (; i < deg; i++) {
        uint4 u0 = *(const uint4*)(base + ((size_t)snb[i] << 8));
        #pragma unroll
        for (int q = 0; q < 4; q++) {
            float2 fv = __half22float2(((const __half2*)&u0)[q]);
            acc[2 * q]     += fv.x;
            acc[2 * q + 1] += fv.y;
        }
    }

    const float inv = 1.0f / ((float)deg + 1e-6f);
    const float4 bf0 = *(const float4*)&bias[f];
    const float4 bf1 = *(const float4*)&bias[f + 4];

    float* dst = &out[((size_t)b * NN + src) * FDIM + f];
    *(float4*)(dst)     = make_float4(acc[0] * inv + bf0.x, acc[1] * inv + bf0.y,
                                      acc[2] * inv + bf0.z, acc[3] * inv + bf0.w);
    *(float4*)(dst + 4) = make_float4(acc[4] * inv + bf1.x, acc[5] * inv + bf1.y,
                                      acc[6] * inv + bf1.z, acc[7] * inv + bf1.w);
}

// ---------------------------------------------------------------------------
extern "C" void kernel_launch(void* const* d_in, const int* in_sizes, int n_in,
                              void* d_out, int out_size) {
    const float* x    = (const float*)d_in[0];   // (8, 4096, 256) f32
    const int*   ei   = (const int*)  d_in[1];   // (2, 131072) i32
    const float* w    = (const float*)d_in[2];   // (256, 256) f32
    const float* bias = (const float*)d_in[3];   // (256,) f32
    float* out = (float*)d_out;

    const int E = in_sizes[1] / 2;

    cudaFuncSetAttribute(k_gemm_tc, cudaFuncAttributeMaxDynamicSharedMemorySize,
                         S_TOT);

    k_edges<<<(E + 255) / 256, 256>>>(ei, w, E);
    k_gemm_tc<<<dim3(2, MTOT / 128), 256, S_TOT>>>(x);
    k_agg<<<NN, 256>>>(bias, out);
}

// round 13
// speedup vs baseline: 1.0584x; 1.0292x over previous
#include <cuda_runtime.h>
#include <cuda_fp16.h>
#include <cstdint>

// Problem constants (fixed by the dataset)
#define NN   4096
#define FDIM 256
#define BB   8
#define MTOT (BB * NN)          // 32768 rows
#define WPR  (NN / 32)
#define MAXD 128

// -------- scratch (static __device__ arrays; no allocation allowed) --------
// g_adj / g_deg are zero-initialized at module load; k_agg's tail re-zeroes
// them each call, so every kernel_launch invocation starts from zero state.
__device__ unsigned g_adj[NN * WPR];
__device__ int      g_deg[NN];
__device__ int      g_nbr[NN * MAXD];
__device__ __align__(16) __half g_xth[(size_t)MTOT * FDIM];  // 16 MB fp16 xt

// ---------------------------------------------------------------------------
// Kernel 1: FUSED edge-build + GEMM.
//   edges: one edge per thread (grid 512x256 == E); atomicOr issued first,
//          finished after the B preload -> latency hidden under tensor work.
//   gemm : xt = x @ W, single-term fp16 mma.sync, fp32 accumulate.
//          B smem stored [k][n] fp16 converted directly from fp32 w
//          (coalesced LDG + STS, no W^T scratch array), fragments loaded
//          with ldmatrix.x4.trans. CTA tile M=128 x N=128.
// ---------------------------------------------------------------------------
#define BSTR2 136                  // B smem row stride in halves (128 + 8 pad)
#define S_TOT (256 * BSTR2 * 2)    // 69632 bytes

extern __shared__ char dsm[];

__device__ __forceinline__ uint32_t smem_u32(const void* p) {
    uint32_t a;
    asm("{ .reg .u64 t; cvta.to.shared.u64 t, %1; cvt.u32.u64 %0, t; }"
        : "=r"(a) : "l"(p));
    return a;
}
__device__ __forceinline__ void ldsm_x4_t(uint32_t* r, uint32_t addr) {
    asm volatile("ldmatrix.sync.aligned.m8n8.x4.trans.shared.b16 {%0,%1,%2,%3}, [%4];"
                 : "=r"(r[0]), "=r"(r[1]), "=r"(r[2]), "=r"(r[3]) : "r"(addr));
}
__device__ __forceinline__ void mma_f16(float* c, const uint32_t* a,
                                        const uint32_t* b) {
    asm volatile(
        "mma.sync.aligned.m16n8k16.row.col.f32.f16.f16.f32 "
        "{%0,%1,%2,%3}, {%4,%5,%6,%7}, {%8,%9}, {%0,%1,%2,%3};"
        : "+f"(c[0]), "+f"(c[1]), "+f"(c[2]), "+f"(c[3])
        : "r"(a[0]), "r"(a[1]), "r"(a[2]), "r"(a[3]), "r"(b[0]), "r"(b[1]));
}

__global__ void __launch_bounds__(256)
k_gemm_tc(const float* __restrict__ x, const float* __restrict__ w,
          const int* __restrict__ ei, int E) {
    const int tid  = threadIdx.x;
    const int lane = tid & 31;
    const int wrp  = tid >> 5;
    const int wm   = wrp >> 1;        // 0..3 (32-row block)
    const int wn   = wrp & 1;         // 0..1 (64-col block)
    const int n0   = blockIdx.x * 128;
    const int m0   = blockIdx.y * 128;
    const uint32_t sb = smem_u32(dsm);

    // ---- edge work, part 1: issue the dedup atomicOr ----
    const int gid = ((blockIdx.y * gridDim.x + blockIdx.x) << 8) + tid;
    int esrc = -1, edst = 0;
    unsigned eold = 0, emask = 0;
    if (gid < E) {
        esrc  = ei[gid];
        edst  = ei[E + gid];
        emask = 1u << (edst & 31);
        eold  = atomicOr(&g_adj[esrc * WPR + (edst >> 5)], emask);
    }

    // ---- B preload: w [k][n0:n0+128] fp32 -> smem [k][n] fp16 (coalesced) ----
    const float* wp = w + n0;
    #pragma unroll
    for (int q = 0; q < 32; q++) {
        int i  = q * 256 + tid;       // float4 index, 0..8191
        int k  = i >> 5;              // 32 float4 per 128-wide row
        int c4 = i & 31;
        float4 f = *(const float4*)(wp + (size_t)k * FDIM + c4 * 4);
        __half2 h0 = __float22half2_rn(make_float2(f.x, f.y));
        __half2 h1 = __float22half2_rn(make_float2(f.z, f.w));
        *(uint2*)(dsm + k * (BSTR2 * 2) + c4 * 8) =
            make_uint2(*(uint32_t*)&h0, *(uint32_t*)&h1);
    }

    // ---- edge work, part 2: finish the dedup chain (latency overlapped) ----
    if (esrc >= 0 && !(eold & emask)) {
        int pos = atomicAdd(&g_deg[esrc], 1);
        if (pos < MAXD) g_nbr[esrc * MAXD + pos] = edst;
    }
    // safety net if E ever exceeds total threads
    for (int e2 = gid + (gridDim.x * gridDim.y << 8); e2 < E;
         e2 += (gridDim.x * gridDim.y << 8)) {
        int s = ei[e2], d = ei[E + e2];
        unsigned mk = 1u << (d & 31);
        unsigned od = atomicOr(&g_adj[s * WPR + (d >> 5)], mk);
        if (!(od & mk)) {
            int pos = atomicAdd(&g_deg[s], 1);
            if (pos < MAXD) g_nbr[s * MAXD + pos] = d;
        }
    }
    __syncthreads();

    // ---- mainloop (round-10 proven structure; B via ldsm.trans) ----
    const float* ap = x + (size_t)(m0 + wm * 32 + (lane >> 2)) * FDIM +
                      ((lane & 3) << 1);
    // trans tiles: lanes0-7: klo/n+0, 8-15: khi/n+0, 16-23: klo/n+8, 24-31: khi/n+8
    const uint32_t bbase = sb +
        (uint32_t)(((lane >> 3) & 1) * 8 + (lane & 7)) * (BSTR2 * 2) +
        (uint32_t)(wn * 64 + ((lane >> 4) & 1) * 8) * 2;

    float acc[2][8][4];
    #pragma unroll
    for (int i = 0; i < 2; i++)
        #pragma unroll
        for (int j = 0; j < 8; j++)
            #pragma unroll
            for (int r = 0; r < 4; r++) acc[i][j][r] = 0.f;

    float2 pv[2][4];
    #pragma unroll
    for (int i = 0; i < 2; i++) {
        const float* p = ap + i * 16 * FDIM;
        pv[i][0] = *(const float2*)(p);
        pv[i][1] = *(const float2*)(p + 8 * FDIM);
        pv[i][2] = *(const float2*)(p + 8);
        pv[i][3] = *(const float2*)(p + 8 * FDIM + 8);
    }

    #pragma unroll
    for (int kk = 0; kk < 16; kk++) {
        float2 nv[2][4];
        if (kk + 1 < 16) {
            const int kn = (kk + 1) * 16;
            #pragma unroll
            for (int i = 0; i < 2; i++) {
                const float* p = ap + i * 16 * FDIM + kn;
                nv[i][0] = *(const float2*)(p);
                nv[i][1] = *(const float2*)(p + 8 * FDIM);
                nv[i][2] = *(const float2*)(p + 8);
                nv[i][3] = *(const float2*)(p + 8 * FDIM + 8);
            }
        }

        uint32_t aF[2][4];
        #pragma unroll
        for (int i = 0; i < 2; i++)
            #pragma unroll
            for (int q = 0; q < 4; q++) {
                __half2 h = __float22half2_rn(pv[i][q]);
                aF[i][q] = *(uint32_t*)&h;
            }

        const uint32_t krow = (uint32_t)(kk * 16) * (BSTR2 * 2);
        #pragma unroll
        for (int j2 = 0; j2 < 4; j2++) {
            uint32_t bb[4];
            ldsm_x4_t(bb, bbase + krow + (uint32_t)(j2 * 16) * 2);
            #pragma unroll
            for (int i = 0; i < 2; i++) {
                mma_f16(acc[i][2 * j2 + 0], aF[i], &bb[0]);
                mma_f16(acc[i][2 * j2 + 1], aF[i], &bb[2]);
            }
        }

        #pragma unroll
        for (int i = 0; i < 2; i++)
            #pragma unroll
            for (int q = 0; q < 4; q++) pv[i][q] = nv[i][q];
    }

    #pragma unroll
    for (int i = 0; i < 2; i++) {
        #pragma unroll
        for (int j = 0; j < 8; j++) {
            int m = m0 + wm * 32 + i * 16 + (lane >> 2);
            int n = n0 + wn * 64 + j * 8 + (lane & 3) * 2;
            *(__half2*)&g_xth[(size_t)m * FDIM + n] =
                __float22half2_rn(make_float2(acc[i][j][0], acc[i][j][1]));
            *(__half2*)&g_xth[(size_t)(m + 8) * FDIM + n] =
                __float22half2_rn(make_float2(acc[i][j][2], acc[i][j][3]));
        }
    }
}

// ---------------------------------------------------------------------------
// Kernel 2: sparse aggregation (round-10 proven 4-way loop) + rezero tail.
// ---------------------------------------------------------------------------
__global__ void __launch_bounds__(256)
k_agg(const float* __restrict__ bias, float* __restrict__ out) {
    const int src  = blockIdx.x;
    const int tid  = threadIdx.x;
    const int b    = tid >> 5;           // batch = warp
    const int lane = tid & 31;
    const int f    = lane << 3;          // 8 features per lane

    __shared__ int snb[MAXD];
    int deg = g_deg[src];
    if (deg > MAXD) deg = MAXD;
    if (tid < deg) snb[tid] = g_nbr[src * MAXD + tid];
    __syncthreads();

    // rezero for the next call (each block owns its src's slots)
    if (tid < WPR) g_adj[src * WPR + tid] = 0u;
    if (tid == 0)  g_deg[src] = 0;

    const __half* __restrict__ base = g_xth + (size_t)b * NN * FDIM + f;

    float acc[8];
    #pragma unroll
    for (int q = 0; q < 8; q++) acc[q] = 0.f;

    int i = 0;
    for (; i + 4 <= deg; i += 4) {
        uint4 u0 = *(const uint4*)(base + ((size_t)snb[i]     << 8));
        uint4 u1 = *(const uint4*)(base + ((size_t)snb[i + 1] << 8));
        uint4 u2 = *(const uint4*)(base + ((size_t)snb[i + 2] << 8));
        uint4 u3 = *(const uint4*)(base + ((size_t)snb[i + 3] << 8));
        #pragma unroll
        for (int q = 0; q < 4; q++) {
            __half2 s01 = __hadd2(((const __half2*)&u0)[q],
                                  ((const __half2*)&u1)[q]);
            __half2 s23 = __hadd2(((const __half2*)&u2)[q],
                                  ((const __half2*)&u3)[q]);
            float2 f01 = __half22float2(s01);
            float2 f23 = __half22float2(s23);
            acc[2 * q]     += f01.x + f23.x;
            acc[2 * q + 1] += f01.y + f23.y;
        }
    }
    for (; i < deg; i++) {
        uint4 u0 = *(const uint4*)(base + ((size_t)snb[i] << 8));
        #pragma unroll
        for (int q = 0; q < 4; q++) {
            float2 fv = __half22float2(((const __half2*)&u0)[q]);
            acc[2 * q]     += fv.x;
            acc[2 * q + 1] += fv.y;
        }
    }

    const float inv = 1.0f / ((float)deg + 1e-6f);
    const float4 bf0 = *(const float4*)&bias[f];
    const float4 bf1 = *(const float4*)&bias[f + 4];

    float* dst = &out[((size_t)b * NN + src) * FDIM + f];
    *(float4*)(dst)     = make_float4(acc[0] * inv + bf0.x, acc[1] * inv + bf0.y,
                                      acc[2] * inv + bf0.z, acc[3] * inv + bf0.w);
    *(float4*)(dst + 4) = make_float4(acc[4] * inv + bf1.x, acc[5] * inv + bf1.y,
                                      acc[6] * inv + bf1.z, acc[7] * inv + bf1.w);
}

// ---------------------------------------------------------------------------
extern "C" void kernel_launch(void* const* d_in, const int* in_sizes, int n_in,
                              void* d_out, int out_size) {
    const float* x    = (const float*)d_in[0];   // (8, 4096, 256) f32
    const int*   ei   = (const int*)  d_in[1];   // (2, 131072) i32
    const float* w    = (const float*)d_in[2];   // (256, 256) f32
    const float* bias = (const float*)d_in[3];   // (256,) f32
    float* out = (float*)d_out;

    const int E = in_sizes[1] / 2;

    cudaFuncSetAttribute(k_gemm_tc, cudaFuncAttributeMaxDynamicSharedMemorySize,
                         S_TOT);

    k_gemm_tc<<<dim3(2, MTOT / 128), 256, S_TOT>>>(x, w, ei, E);
    k_agg<<<NN, 256>>>(bias, out);
}